// round 9
// baseline (speedup 1.0000x reference)
#include <cuda_runtime.h>
#include <cuda_fp16.h>
#include <cstdint>
#include <cstddef>

#define NN 8192
#define OUT_DIM 64
#define IN_DIM 256
#define KB 8                  // K-split across grid.x
#define KSLAB (NN / KB)       // 1024
#define MTILE 64              // rows per CTA (4 warps x 16)
#define NWARP 4
#define APITCH 68             // smem ints per staged A row
#define NIT (KSLAB / 64)      // 16 stages
#define ASTB (16 * APITCH * 4)   // bytes per A stage per warp = 4352

// ---------------- device scratch ----------------
__device__ float g_Wh[(size_t)NN * OUT_DIM];
__device__ float g_f1[NN];
__device__ float g_f2[NN];
__device__ float2 g_EG1[NN];                 // {S*exp(f1), S*exp(0.2 f1)}
__device__ float2 g_EG2[NN];                 // {exp(f2), exp(0.2 f2)}
__device__ uint4 g_Bfrag[512 * 4 * 32];      // Wh in fp16 mma-B-fragment layout (1 MB)
__device__ float g_num[(size_t)KB * NN * OUT_DIM];   // 16.8 MB
__device__ float g_den[KB * NN];

typedef unsigned long long ull;

// ---------------- helpers ----------------
__device__ __forceinline__ void mma16816(float* d, uint32_t a0, uint32_t a1,
                                         uint32_t a2, uint32_t a3,
                                         uint32_t b0, uint32_t b1) {
    asm volatile(
        "mma.sync.aligned.m16n8k16.row.col.f32.f16.f16.f32 "
        "{%0,%1,%2,%3},{%4,%5,%6,%7},{%8,%9},{%0,%1,%2,%3};"
        : "+f"(d[0]), "+f"(d[1]), "+f"(d[2]), "+f"(d[3])
        : "r"(a0), "r"(a1), "r"(a2), "r"(a3), "r"(b0), "r"(b1));
}
__device__ __forceinline__ uint32_t packh2(float lo, float hi) {
    __half2 h = __floats2half2_rn(lo, hi);
    return *reinterpret_cast<uint32_t*>(&h);
}
__device__ __forceinline__ ull pkf2(float x, float y) {
    ull r; asm("mov.b64 %0, {%1, %2};" : "=l"(r) : "f"(x), "f"(y)); return r;
}
// max of (a.x*b.x, a.y*b.y) with one packed multiply
__device__ __forceinline__ float wmax2(ull a, ull b) {
    ull p; float lo, hi;
    asm("mul.rn.f32x2 %0, %1, %2;" : "=l"(p) : "l"(a), "l"(b));
    asm("mov.b64 {%0, %1}, %2;" : "=f"(lo), "=f"(hi) : "l"(p));
    return fmaxf(lo, hi);
}
__device__ __forceinline__ uint32_t s2u(const void* p) {
    uint32_t a;
    asm("{ .reg .u64 t; cvta.to.shared.u64 t, %1; cvt.u32.u64 %0, t; }" : "=r"(a) : "l"(p));
    return a;
}
__device__ __forceinline__ void cpasync16(uint32_t smem, const void* g) {
    asm volatile("cp.async.cg.shared.global [%0], [%1], 16;" :: "r"(smem), "l"(g) : "memory");
}
#define CP_COMMIT() asm volatile("cp.async.commit_group;" ::: "memory")
#define CP_WAIT1()  asm volatile("cp.async.wait_group 1;" ::: "memory")

// ================= K1: Wh = h@W, f1, f2 =================
extern __shared__ float k1sm[];
__global__ void k1_wh(const float* __restrict__ h, const float* __restrict__ W,
                      const float* __restrict__ a) {
    float* Ws = k1sm;                      // [256][64]
    float* hs = k1sm + IN_DIM * OUT_DIM;   // [64][260]
    int tid = threadIdx.x;
    int row = tid >> 2, cs = (tid & 3) * 16;
    int row0 = blockIdx.x * 64;

    for (int t = tid; t < IN_DIM * OUT_DIM / 4; t += 256)
        ((float4*)Ws)[t] = ((const float4*)W)[t];
    for (int t = tid; t < 64 * IN_DIM / 4; t += 256) {
        int r = t >> 6, c = (t & 63) * 4;
        *(float4*)(hs + r * 260 + c) = *(const float4*)(h + (((size_t)(row0 + r)) << 8) + c);
    }
    __syncthreads();

    float4 acc[4];
#pragma unroll
    for (int q = 0; q < 4; q++) acc[q] = make_float4(0.f, 0.f, 0.f, 0.f);

#pragma unroll 4
    for (int k = 0; k < IN_DIM; k++) {
        float hv = hs[row * 260 + k];
        const float4* wr = (const float4*)(Ws + k * OUT_DIM + cs);
#pragma unroll
        for (int q = 0; q < 4; q++) {
            float4 w4 = wr[q];
            acc[q].x = fmaf(hv, w4.x, acc[q].x);
            acc[q].y = fmaf(hv, w4.y, acc[q].y);
            acc[q].z = fmaf(hv, w4.z, acc[q].z);
            acc[q].w = fmaf(hv, w4.w, acc[q].w);
        }
    }

    float4* wout = (float4*)(g_Wh + (size_t)(row0 + row) * OUT_DIM + cs);
#pragma unroll
    for (int q = 0; q < 4; q++) wout[q] = acc[q];

    float s1 = 0.f, s2 = 0.f;
#pragma unroll
    for (int q = 0; q < 4; q++) {
        const float* ap = a + cs + q * 4;
        const float* bp = a + OUT_DIM + cs + q * 4;
        float v[4] = {acc[q].x, acc[q].y, acc[q].z, acc[q].w};
#pragma unroll
        for (int c = 0; c < 4; c++) { s1 = fmaf(v[c], ap[c], s1); s2 = fmaf(v[c], bp[c], s2); }
    }
    s1 += __shfl_xor_sync(~0u, s1, 1); s1 += __shfl_xor_sync(~0u, s1, 2);
    s2 += __shfl_xor_sync(~0u, s2, 1); s2 += __shfl_xor_sync(~0u, s2, 2);
    if ((tid & 3) == 0) { g_f1[row0 + row] = s1; g_f2[row0 + row] = s2; }
}

// ========== K1bc: blocks [0,256): B fragments; [256,288): exp vectors ==========
#define FRAG_BLOCKS 256
__global__ void __launch_bounds__(256) k1bc(void) {
    int bx = blockIdx.x, tid = threadIdx.x;

    if (bx < FRAG_BLOCKS) {
        __shared__ float whs[2][16 * 64];
        int half = tid >> 7, t = tid & 127;
        int kc = bx * 2 + half;
        const float4* src = (const float4*)(g_Wh + (size_t)kc * 16 * 64);
        float4* dst = (float4*)whs[half];
        dst[t] = src[t];
        dst[t + 128] = src[t + 128];
        __syncthreads();

        int p = (t >> 5) & 3, lane = t & 31;
        int lk = (lane & 3) * 2;
        int n0 = p * 16 + (lane >> 2);
        int n1 = n0 + 8;
        const float* w = whs[half];
        uint4 o;
        o.x = packh2(w[lk * 64 + n0],       w[(lk + 1) * 64 + n0]);
        o.y = packh2(w[(lk + 8) * 64 + n0], w[(lk + 9) * 64 + n0]);
        o.z = packh2(w[lk * 64 + n1],       w[(lk + 1) * 64 + n1]);
        o.w = packh2(w[(lk + 8) * 64 + n1], w[(lk + 9) * 64 + n1]);
        g_Bfrag[(kc * 4 + p) * 32 + lane] = o;
    } else {
        __shared__ float m1s[8], m2s[8], lss;
        float m1 = -1e30f, m2 = -1e30f;
        for (int i = tid; i < NN; i += 256) {
            m1 = fmaxf(m1, g_f1[i]);
            m2 = fmaxf(m2, g_f2[i]);
        }
#pragma unroll
        for (int o = 16; o; o >>= 1) {
            m1 = fmaxf(m1, __shfl_xor_sync(~0u, m1, o));
            m2 = fmaxf(m2, __shfl_xor_sync(~0u, m2, o));
        }
        if ((tid & 31) == 0) { m1s[tid >> 5] = m1; m2s[tid >> 5] = m2; }
        __syncthreads();
        if (tid == 0) {
            float a1 = m1s[0], a2 = m2s[0];
#pragma unroll
            for (int i = 1; i < 8; i++) { a1 = fmaxf(a1, m1s[i]); a2 = fmaxf(a2, m2s[i]); }
            lss = logf(49000.f) - a1 - a2;
        }
        __syncthreads();
        float ls = lss;
        int i = (bx - FRAG_BLOCKS) * 256 + tid;
        float f1 = g_f1[i], f2 = g_f2[i];
        g_EG1[i] = make_float2(expf(f1 + ls), expf(0.2f * f1 + ls));
        g_EG2[i] = make_float2(expf(f2), expf(0.2f * f2));
    }
}

// ========== dummy kernel: keeps k2_attn as the 4th launch for ncu ==========
__global__ void dnoop(void) {}

// ================= K2: masked attention, HMMA, 128-thr CTA, high occupancy =================
// smem: per-warp 2-stage A rings only (4 warps x 2 x 4352 = 34816 B)
extern __shared__ char k2smraw[];
__global__ void __launch_bounds__(128, 6) k2_attn(const int* __restrict__ A) {
    int tid = threadIdx.x, wid = tid >> 5, lane = tid & 31;
    int kb = blockIdx.x;
    int rowBase = blockIdx.y * MTILE;
    uint32_t sb = s2u(k2smraw);

    int r_lo = lane >> 2;
    int q2 = (lane & 3) * 2;
    int myrow = rowBase + wid * 16;
    float2 e1t = g_EG1[myrow + r_lo];
    float2 e1u = g_EG1[myrow + r_lo + 8];
    ull eg1a = pkf2(e1t.x, e1t.y);
    ull eg1b = pkf2(e1u.x, e1u.y);

    float acc[8][4];
#pragma unroll
    for (int n = 0; n < 8; n++)
#pragma unroll
        for (int c = 0; c < 4; c++) acc[n][c] = 0.f;
    float dn0 = 0.f, dn1 = 0.f;

    const int* Arow = A + (size_t)myrow * NN + kb * KSLAB;
    int ldRow = lane >> 4;                 // 0..1
    int ldSeg = (lane & 15) * 4;           // int offset 0..60
    uint32_t aRing = sb + wid * (2 * ASTB);
    const uint4* __restrict__ Bbase = g_Bfrag + (size_t)kb * (KSLAB / 16) * 128 + lane;
    const char* __restrict__ egbase = (const char*)(g_EG2 + (size_t)kb * KSLAB);

#define A_STAGE(s, slot) do {                                                     \
        int _c0 = (s) * 64;                                                       \
        uint32_t _ad = aRing + (slot) * ASTB;                                     \
        _Pragma("unroll")                                                         \
        for (int _L = 0; _L < 8; _L++)                                            \
            cpasync16(_ad + ((_L * 2 + ldRow) * APITCH + ldSeg) * 4,              \
                      Arow + (size_t)(_L * 2 + ldRow) * NN + _c0 + ldSeg);        \
        CP_COMMIT();                                                              \
    } while (0)

    A_STAGE(0, 0);
    A_STAGE(1, 1);

    // B prefetch for chunk 0 (consumed directly; refilled after each use)
    uint4 Bpf[4];
#pragma unroll
    for (int p = 0; p < 4; p++) Bpf[p] = __ldg(Bbase + p * 32);

#pragma unroll 1
    for (int it = 0; it < NIT; ++it) {
        CP_WAIT1();
        __syncwarp();
        const int* Aw = (const int*)(k2smraw + wid * (2 * ASTB) + (it & 1) * ASTB);

#pragma unroll
        for (int ck = 0; ck < 4; ++ck) {
            int c = it * 4 + ck;
            int cl = c * 16;
            ulonglong2 EA = *(const ulonglong2*)(egbase + (size_t)(cl + q2) * 8);
            ulonglong2 EB = *(const ulonglong2*)(egbase + (size_t)(cl + q2 + 8) * 8);
            int base = ck * 16 + q2;
            int2 aL0 = *(const int2*)(Aw + r_lo * APITCH + base);
            int2 aL1 = *(const int2*)(Aw + r_lo * APITCH + base + 8);
            int2 aH0 = *(const int2*)(Aw + (r_lo + 8) * APITCH + base);
            int2 aH1 = *(const int2*)(Aw + (r_lo + 8) * APITCH + base + 8);

            float w00 = (aL0.x > 0) ? wmax2(eg1a, EA.x) : 0.f;
            float w01 = (aL0.y > 0) ? wmax2(eg1a, EA.y) : 0.f;
            float w02 = (aL1.x > 0) ? wmax2(eg1a, EB.x) : 0.f;
            float w03 = (aL1.y > 0) ? wmax2(eg1a, EB.y) : 0.f;
            float w10 = (aH0.x > 0) ? wmax2(eg1b, EA.x) : 0.f;
            float w11 = (aH0.y > 0) ? wmax2(eg1b, EA.y) : 0.f;
            float w12 = (aH1.x > 0) ? wmax2(eg1b, EB.x) : 0.f;
            float w13 = (aH1.y > 0) ? wmax2(eg1b, EB.y) : 0.f;

            dn0 += (w00 + w01) + (w02 + w03);
            dn1 += (w10 + w11) + (w12 + w13);

            uint32_t a0 = packh2(w00, w01);
            uint32_t a1 = packh2(w10, w11);
            uint32_t a2 = packh2(w02, w03);
            uint32_t a3 = packh2(w12, w13);

            // consume current B prefetch (mma reads regs at issue), then refill
            mma16816(acc[0], a0, a1, a2, a3, Bpf[0].x, Bpf[0].y);
            mma16816(acc[1], a0, a1, a2, a3, Bpf[0].z, Bpf[0].w);
            mma16816(acc[2], a0, a1, a2, a3, Bpf[1].x, Bpf[1].y);
            mma16816(acc[3], a0, a1, a2, a3, Bpf[1].z, Bpf[1].w);
            mma16816(acc[4], a0, a1, a2, a3, Bpf[2].x, Bpf[2].y);
            mma16816(acc[5], a0, a1, a2, a3, Bpf[2].z, Bpf[2].w);
            mma16816(acc[6], a0, a1, a2, a3, Bpf[3].x, Bpf[3].y);
            mma16816(acc[7], a0, a1, a2, a3, Bpf[3].z, Bpf[3].w);

            if (c + 1 < 4 * NIT) {
                const uint4* Bp = Bbase + (size_t)(c + 1) * 128;
#pragma unroll
                for (int p = 0; p < 4; p++) Bpf[p] = __ldg(Bp + p * 32);
            }
        }
        __syncwarp();
        if (it + 2 < NIT) A_STAGE(it + 2, it & 1);
        else CP_COMMIT();     // keep wait_group accounting uniform
    }

    // denominator (fp32-exact)
    dn0 += __shfl_xor_sync(~0u, dn0, 1); dn0 += __shfl_xor_sync(~0u, dn0, 2);
    dn1 += __shfl_xor_sync(~0u, dn1, 1); dn1 += __shfl_xor_sync(~0u, dn1, 2);
    if ((lane & 3) == 0) {
        g_den[kb * NN + myrow + r_lo] = dn0;
        g_den[kb * NN + myrow + r_lo + 8] = dn1;
    }
    // numerator partials
    float* np = g_num + ((size_t)kb * NN + myrow) * OUT_DIM;
#pragma unroll
    for (int nt = 0; nt < 8; nt++) {
        int col = nt * 8 + q2;
        *(float2*)(np + (size_t)r_lo * OUT_DIM + col)       = make_float2(acc[nt][0], acc[nt][1]);
        *(float2*)(np + (size_t)(r_lo + 8) * OUT_DIM + col) = make_float2(acc[nt][2], acc[nt][3]);
    }
}

// ================= K3: reduce, normalize, elu =================
__global__ void k3_fin(float* __restrict__ out) {
    int gid = blockIdx.x * 256 + threadIdx.x;
    int base = gid * 4;
    int row = base >> 6;
    float4 s = make_float4(0.f, 0.f, 0.f, 0.f);
    float d = 0.f;
#pragma unroll
    for (int c = 0; c < KB; c++) {
        float4 v = *(const float4*)(g_num + (size_t)c * NN * OUT_DIM + base);
        s.x += v.x; s.y += v.y; s.z += v.z; s.w += v.w;
        d += g_den[c * NN + row];
    }
    float inv = 1.f / d;
    float4 o;
    o.x = s.x * inv; o.y = s.y * inv; o.z = s.z * inv; o.w = s.w * inv;
    o.x = o.x > 0.f ? o.x : expm1f(o.x);
    o.y = o.y > 0.f ? o.y : expm1f(o.y);
    o.z = o.z > 0.f ? o.z : expm1f(o.z);
    o.w = o.w > 0.f ? o.w : expm1f(o.w);
    *(float4*)(out + base) = o;
}

// ================= launch =================
extern "C" void kernel_launch(void* const* d_in, const int* in_sizes, int n_in,
                              void* d_out, int out_size) {
    const float* h = nullptr; const int* A = nullptr;
    const float* W = nullptr; const float* a = nullptr;
    for (int i = 0; i < n_in; i++) {
        if      (in_sizes[i] == NN * IN_DIM)      h = (const float*)d_in[i];
        else if (in_sizes[i] == IN_DIM * OUT_DIM) W = (const float*)d_in[i];
        else if (in_sizes[i] == 2 * OUT_DIM)      a = (const float*)d_in[i];
        else                                      A = (const int*)d_in[i];
    }
    float* out = (float*)d_out;

    const int k1_smem = (IN_DIM * OUT_DIM + 64 * 260) * (int)sizeof(float);
    cudaFuncSetAttribute(k1_wh, cudaFuncAttributeMaxDynamicSharedMemorySize, k1_smem);
    const int k2_smem = NWARP * 2 * ASTB;   // 34816
    cudaFuncSetAttribute(k2_attn, cudaFuncAttributeMaxDynamicSharedMemorySize, k2_smem);

    k1_wh<<<NN / 64, 256, k1_smem>>>(h, W, a);
    k1bc<<<FRAG_BLOCKS + NN / 256, 256>>>();
    dnoop<<<1, 32>>>();                       // position k2 as 4th launch for ncu
    dim3 g2(KB, NN / MTILE);
    k2_attn<<<g2, 128, k2_smem>>>(A);
    k3_fin<<<(NN * OUT_DIM) / 1024, 256>>>(out);
}

// round 10
// speedup vs baseline: 1.5912x; 1.5912x over previous
#include <cuda_runtime.h>
#include <cuda_fp16.h>
#include <cstdint>
#include <cstddef>

#define NN 8192
#define OUT_DIM 64
#define IN_DIM 256
#define KB 4                  // K-split across grid.x
#define KSLAB (NN / KB)       // 2048
#define MTILE 128             // rows per CTA
#define APITCH 68             // smem ints per staged A row
#define NIT (KSLAB / 64)      // 32 stages
#define ASTB (16 * APITCH * 4)   // bytes per A stage per warp = 4352

// ---------------- device scratch ----------------
__device__ float g_Wh[(size_t)NN * OUT_DIM];
__device__ float g_f1[NN];
__device__ float g_f2[NN];
__device__ float2 g_EG1[NN];                 // {S*exp(f1), S*exp(0.2 f1)}
__device__ float2 g_EG2[NN];                 // {exp(f2), exp(0.2 f2)}
__device__ uint4 g_Bfrag[512 * 4 * 32];      // Wh in fp16 mma-B-fragment layout (1 MB)
__device__ float g_num[(size_t)KB * NN * OUT_DIM];
__device__ float g_den[KB * NN];

// ---------------- helpers ----------------
__device__ __forceinline__ void mma16816(float* d, uint32_t a0, uint32_t a1,
                                         uint32_t a2, uint32_t a3,
                                         uint32_t b0, uint32_t b1) {
    asm volatile(
        "mma.sync.aligned.m16n8k16.row.col.f32.f16.f16.f32 "
        "{%0,%1,%2,%3},{%4,%5,%6,%7},{%8,%9},{%0,%1,%2,%3};"
        : "+f"(d[0]), "+f"(d[1]), "+f"(d[2]), "+f"(d[3])
        : "r"(a0), "r"(a1), "r"(a2), "r"(a3), "r"(b0), "r"(b1));
}
__device__ __forceinline__ uint32_t packh2(float lo, float hi) {
    __half2 h = __floats2half2_rn(lo, hi);
    return *reinterpret_cast<uint32_t*>(&h);
}
__device__ __forceinline__ uint32_t s2u(const void* p) {
    uint32_t a;
    asm("{ .reg .u64 t; cvta.to.shared.u64 t, %1; cvt.u32.u64 %0, t; }" : "=r"(a) : "l"(p));
    return a;
}
__device__ __forceinline__ void cpasync16(uint32_t smem, const void* g) {
    asm volatile("cp.async.cg.shared.global [%0], [%1], 16;" :: "r"(smem), "l"(g) : "memory");
}
#define CP_COMMIT() asm volatile("cp.async.commit_group;" ::: "memory")
#define CP_WAIT1()  asm volatile("cp.async.wait_group 1;" ::: "memory")

// ================= K1: Wh = h@W, f1, f2  (4x4 register blocking) =================
extern __shared__ float k1sm[];
__global__ void __launch_bounds__(256) k1_wh(const float* __restrict__ h,
                                             const float* __restrict__ W,
                                             const float* __restrict__ a) {
    float* Ws = k1sm;                      // [256][64]
    float* hs = k1sm + IN_DIM * OUT_DIM;   // [64][260]
    int tid = threadIdx.x;
    int rg = tid >> 4;                     // 16 row groups x 4 rows
    int cg = tid & 15;                     // 16 col groups x 4 cols
    int row0 = blockIdx.x * 64;

    for (int t = tid; t < IN_DIM * OUT_DIM / 4; t += 256)
        ((float4*)Ws)[t] = ((const float4*)W)[t];
    for (int t = tid; t < 64 * IN_DIM / 4; t += 256) {
        int r = t >> 6, c = (t & 63) * 4;
        *(float4*)(hs + r * 260 + c) = *(const float4*)(h + (((size_t)(row0 + r)) << 8) + c);
    }
    __syncthreads();

    float4 acc[4];
#pragma unroll
    for (int r = 0; r < 4; r++) acc[r] = make_float4(0.f, 0.f, 0.f, 0.f);

#pragma unroll 2
    for (int kk = 0; kk < IN_DIM; kk += 4) {
        float4 w0 = *(const float4*)(Ws + (kk + 0) * OUT_DIM + cg * 4);
        float4 w1 = *(const float4*)(Ws + (kk + 1) * OUT_DIM + cg * 4);
        float4 w2 = *(const float4*)(Ws + (kk + 2) * OUT_DIM + cg * 4);
        float4 w3 = *(const float4*)(Ws + (kk + 3) * OUT_DIM + cg * 4);
#pragma unroll
        for (int r = 0; r < 4; r++) {
            float4 hq = *(const float4*)(hs + (rg * 4 + r) * 260 + kk);
            acc[r].x = fmaf(hq.x, w0.x, acc[r].x);
            acc[r].y = fmaf(hq.x, w0.y, acc[r].y);
            acc[r].z = fmaf(hq.x, w0.z, acc[r].z);
            acc[r].w = fmaf(hq.x, w0.w, acc[r].w);
            acc[r].x = fmaf(hq.y, w1.x, acc[r].x);
            acc[r].y = fmaf(hq.y, w1.y, acc[r].y);
            acc[r].z = fmaf(hq.y, w1.z, acc[r].z);
            acc[r].w = fmaf(hq.y, w1.w, acc[r].w);
            acc[r].x = fmaf(hq.z, w2.x, acc[r].x);
            acc[r].y = fmaf(hq.z, w2.y, acc[r].y);
            acc[r].z = fmaf(hq.z, w2.z, acc[r].z);
            acc[r].w = fmaf(hq.z, w2.w, acc[r].w);
            acc[r].x = fmaf(hq.w, w3.x, acc[r].x);
            acc[r].y = fmaf(hq.w, w3.y, acc[r].y);
            acc[r].z = fmaf(hq.w, w3.z, acc[r].z);
            acc[r].w = fmaf(hq.w, w3.w, acc[r].w);
        }
    }

    // store Wh and reduce f1/f2 across the 16 col-groups (lanes xor 1,2,4,8)
    float4 a1v = *(const float4*)(a + cg * 4);
    float4 a2v = *(const float4*)(a + OUT_DIM + cg * 4);
#pragma unroll
    for (int r = 0; r < 4; r++) {
        int row = row0 + rg * 4 + r;
        *(float4*)(g_Wh + (size_t)row * OUT_DIM + cg * 4) = acc[r];
        float s1 = acc[r].x * a1v.x + acc[r].y * a1v.y + acc[r].z * a1v.z + acc[r].w * a1v.w;
        float s2 = acc[r].x * a2v.x + acc[r].y * a2v.y + acc[r].z * a2v.z + acc[r].w * a2v.w;
#pragma unroll
        for (int o = 1; o < 16; o <<= 1) {
            s1 += __shfl_xor_sync(~0u, s1, o);
            s2 += __shfl_xor_sync(~0u, s2, o);
        }
        if (cg == 0) { g_f1[row] = s1; g_f2[row] = s2; }
    }
}

// ========== K1bc: blocks [0,256): B fragments; [256,288): exp vectors ==========
#define FRAG_BLOCKS 256
__global__ void __launch_bounds__(256) k1bc(void) {
    int bx = blockIdx.x, tid = threadIdx.x;

    if (bx < FRAG_BLOCKS) {
        __shared__ float whs[2][16 * 64];
        int half = tid >> 7, t = tid & 127;
        int kc = bx * 2 + half;
        const float4* src = (const float4*)(g_Wh + (size_t)kc * 16 * 64);
        float4* dst = (float4*)whs[half];
        dst[t] = src[t];
        dst[t + 128] = src[t + 128];
        __syncthreads();

        int p = (t >> 5) & 3, lane = t & 31;
        int lk = (lane & 3) * 2;
        int n0 = p * 16 + (lane >> 2);
        int n1 = n0 + 8;
        const float* w = whs[half];
        uint4 o;
        o.x = packh2(w[lk * 64 + n0],       w[(lk + 1) * 64 + n0]);
        o.y = packh2(w[(lk + 8) * 64 + n0], w[(lk + 9) * 64 + n0]);
        o.z = packh2(w[lk * 64 + n1],       w[(lk + 1) * 64 + n1]);
        o.w = packh2(w[(lk + 8) * 64 + n1], w[(lk + 9) * 64 + n1]);
        g_Bfrag[(kc * 4 + p) * 32 + lane] = o;
    } else {
        __shared__ float m1s[8], m2s[8], lss;
        float m1 = -1e30f, m2 = -1e30f;
        for (int i = tid; i < NN; i += 256) {
            m1 = fmaxf(m1, g_f1[i]);
            m2 = fmaxf(m2, g_f2[i]);
        }
#pragma unroll
        for (int o = 16; o; o >>= 1) {
            m1 = fmaxf(m1, __shfl_xor_sync(~0u, m1, o));
            m2 = fmaxf(m2, __shfl_xor_sync(~0u, m2, o));
        }
        if ((tid & 31) == 0) { m1s[tid >> 5] = m1; m2s[tid >> 5] = m2; }
        __syncthreads();
        if (tid == 0) {
            float a1 = m1s[0], a2 = m2s[0];
#pragma unroll
            for (int i = 1; i < 8; i++) { a1 = fmaxf(a1, m1s[i]); a2 = fmaxf(a2, m2s[i]); }
            lss = logf(49000.f) - a1 - a2;
        }
        __syncthreads();
        float ls = lss;
        int i = (bx - FRAG_BLOCKS) * 256 + tid;
        float f1 = g_f1[i], f2 = g_f2[i];
        g_EG1[i] = make_float2(expf(f1 + ls), expf(0.2f * f1 + ls));
        g_EG2[i] = make_float2(expf(f2), expf(0.2f * f2));
    }
}

// ========== dummy kernel: keeps k2_attn as the 4th launch for ncu ==========
__global__ void dnoop(void) {}

// ================= K2: masked attention, HMMA, barrier-free per-warp pipeline =================
// (exact R7 configuration: KB=4, 256-thr CTA, 2-stage per-warp ring, B reg double-buffer)
// smem bytes: EG2 [0,16384) | per-warp A rings [16384, 86016)
#define SM_A0 16384
extern __shared__ char k2smraw[];
__global__ void __launch_bounds__(256, 2) k2_attn(const int* __restrict__ A) {
    float2* EG2s = (float2*)k2smraw;
    int tid = threadIdx.x, wid = tid >> 5, lane = tid & 31;
    int kb = blockIdx.x;
    int rowBase = blockIdx.y * MTILE;
    uint32_t sb = s2u(k2smraw);

    for (int i = tid; i < KSLAB; i += 256) EG2s[i] = g_EG2[kb * KSLAB + i];

    int r_lo = lane >> 2;
    int q2 = (lane & 3) * 2;
    int myrow = rowBase + wid * 16;
    float2 eg1a = g_EG1[myrow + r_lo];
    float2 eg1b = g_EG1[myrow + r_lo + 8];

    float acc[8][4];
#pragma unroll
    for (int n = 0; n < 8; n++)
#pragma unroll
        for (int c = 0; c < 4; c++) acc[n][c] = 0.f;
    float dn0 = 0.f, dn1 = 0.f;

    const int* Arow = A + (size_t)myrow * NN + kb * KSLAB;
    int ldRow = lane >> 4;                 // 0..1
    int ldSeg = (lane & 15) * 4;           // int offset 0..60
    uint32_t aRing = sb + SM_A0 + wid * (2 * ASTB);
    const uint4* Bbase = g_Bfrag + (size_t)kb * (KSLAB / 16) * 128 + lane;

#define A_STAGE(s) do {                                                           \
        int _c0 = (s) * 64;                                                       \
        uint32_t _ad = aRing + ((s) & 1) * ASTB;                                  \
        _Pragma("unroll")                                                         \
        for (int _L = 0; _L < 8; _L++)                                            \
            cpasync16(_ad + ((_L * 2 + ldRow) * APITCH + ldSeg) * 4,              \
                      Arow + (size_t)(_L * 2 + ldRow) * NN + _c0 + ldSeg);        \
        CP_COMMIT();                                                              \
    } while (0)

    A_STAGE(0);
    A_STAGE(1);

    __syncthreads();   // EG2s visibility (once)

    // B prefetch for chunk 0
    uint4 Bpf[4];
#pragma unroll
    for (int p = 0; p < 4; p++) Bpf[p] = __ldg(Bbase + p * 32);

#pragma unroll 1
    for (int it = 0; it < NIT; ++it) {
        CP_WAIT1();
        __syncwarp();

        const int* Aw = (const int*)(k2smraw + SM_A0 + wid * (2 * ASTB) + (it & 1) * ASTB);

#pragma unroll
        for (int ck = 0; ck < 4; ++ck) {
            int c = it * 4 + ck;
            // consume current prefetch, immediately start next
            uint4 B0 = Bpf[0], B1 = Bpf[1], B2 = Bpf[2], B3 = Bpf[3];
            if (c + 1 < 4 * NIT) {
                const uint4* Bp = Bbase + (size_t)(c + 1) * 128;
#pragma unroll
                for (int p = 0; p < 4; p++) Bpf[p] = __ldg(Bp + p * 32);
            }

            int cl = c * 16;
            float4 egA = *(const float4*)(&EG2s[cl + q2]);
            float4 egB = *(const float4*)(&EG2s[cl + q2 + 8]);
            int base = ck * 16 + q2;
            int2 aL0 = *(const int2*)(Aw + r_lo * APITCH + base);
            int2 aL1 = *(const int2*)(Aw + r_lo * APITCH + base + 8);
            int2 aH0 = *(const int2*)(Aw + (r_lo + 8) * APITCH + base);
            int2 aH1 = *(const int2*)(Aw + (r_lo + 8) * APITCH + base + 8);

            float w00 = (aL0.x > 0) ? fmaxf(eg1a.x * egA.x, eg1a.y * egA.y) : 0.f;
            float w01 = (aL0.y > 0) ? fmaxf(eg1a.x * egA.z, eg1a.y * egA.w) : 0.f;
            float w02 = (aL1.x > 0) ? fmaxf(eg1a.x * egB.x, eg1a.y * egB.y) : 0.f;
            float w03 = (aL1.y > 0) ? fmaxf(eg1a.x * egB.z, eg1a.y * egB.w) : 0.f;
            float w10 = (aH0.x > 0) ? fmaxf(eg1b.x * egA.x, eg1b.y * egA.y) : 0.f;
            float w11 = (aH0.y > 0) ? fmaxf(eg1b.x * egA.z, eg1b.y * egA.w) : 0.f;
            float w12 = (aH1.x > 0) ? fmaxf(eg1b.x * egB.x, eg1b.y * egB.y) : 0.f;
            float w13 = (aH1.y > 0) ? fmaxf(eg1b.x * egB.z, eg1b.y * egB.w) : 0.f;

            dn0 += (w00 + w01) + (w02 + w03);
            dn1 += (w10 + w11) + (w12 + w13);

            uint32_t a0 = packh2(w00, w01);
            uint32_t a1 = packh2(w10, w11);
            uint32_t a2 = packh2(w02, w03);
            uint32_t a3 = packh2(w12, w13);

            mma16816(acc[0], a0, a1, a2, a3, B0.x, B0.y);
            mma16816(acc[1], a0, a1, a2, a3, B0.z, B0.w);
            mma16816(acc[2], a0, a1, a2, a3, B1.x, B1.y);
            mma16816(acc[3], a0, a1, a2, a3, B1.z, B1.w);
            mma16816(acc[4], a0, a1, a2, a3, B2.x, B2.y);
            mma16816(acc[5], a0, a1, a2, a3, B2.z, B2.w);
            mma16816(acc[6], a0, a1, a2, a3, B3.x, B3.y);
            mma16816(acc[7], a0, a1, a2, a3, B3.z, B3.w);
        }
        __syncwarp();
        if (it + 2 < NIT) A_STAGE(it + 2);
        else CP_COMMIT();     // keep wait_group accounting uniform
    }

    // denominator (fp32-exact)
    dn0 += __shfl_xor_sync(~0u, dn0, 1); dn0 += __shfl_xor_sync(~0u, dn0, 2);
    dn1 += __shfl_xor_sync(~0u, dn1, 1); dn1 += __shfl_xor_sync(~0u, dn1, 2);
    if ((lane & 3) == 0) {
        g_den[kb * NN + myrow + r_lo] = dn0;
        g_den[kb * NN + myrow + r_lo + 8] = dn1;
    }
    // numerator partials
    float* np = g_num + ((size_t)kb * NN + myrow) * OUT_DIM;
#pragma unroll
    for (int nt = 0; nt < 8; nt++) {
        int col = nt * 8 + q2;
        *(float2*)(np + (size_t)r_lo * OUT_DIM + col)       = make_float2(acc[nt][0], acc[nt][1]);
        *(float2*)(np + (size_t)(r_lo + 8) * OUT_DIM + col) = make_float2(acc[nt][2], acc[nt][3]);
    }
}

// ================= K3: reduce, normalize, elu =================
__global__ void k3_fin(float* __restrict__ out) {
    int gid = blockIdx.x * 256 + threadIdx.x;
    int base = gid * 4;
    int row = base >> 6;
    float4 s = make_float4(0.f, 0.f, 0.f, 0.f);
    float d = 0.f;
#pragma unroll
    for (int c = 0; c < KB; c++) {
        float4 v = *(const float4*)(g_num + (size_t)c * NN * OUT_DIM + base);
        s.x += v.x; s.y += v.y; s.z += v.z; s.w += v.w;
        d += g_den[c * NN + row];
    }
    float inv = 1.f / d;
    float4 o;
    o.x = s.x * inv; o.y = s.y * inv; o.z = s.z * inv; o.w = s.w * inv;
    o.x = o.x > 0.f ? o.x : expm1f(o.x);
    o.y = o.y > 0.f ? o.y : expm1f(o.y);
    o.z = o.z > 0.f ? o.z : expm1f(o.z);
    o.w = o.w > 0.f ? o.w : expm1f(o.w);
    *(float4*)(out + base) = o;
}

// ================= launch =================
extern "C" void kernel_launch(void* const* d_in, const int* in_sizes, int n_in,
                              void* d_out, int out_size) {
    const float* h = nullptr; const int* A = nullptr;
    const float* W = nullptr; const float* a = nullptr;
    for (int i = 0; i < n_in; i++) {
        if      (in_sizes[i] == NN * IN_DIM)      h = (const float*)d_in[i];
        else if (in_sizes[i] == IN_DIM * OUT_DIM) W = (const float*)d_in[i];
        else if (in_sizes[i] == 2 * OUT_DIM)      a = (const float*)d_in[i];
        else                                      A = (const int*)d_in[i];
    }
    float* out = (float*)d_out;

    const int k1_smem = (IN_DIM * OUT_DIM + 64 * 260) * (int)sizeof(float);  // 132096
    cudaFuncSetAttribute(k1_wh, cudaFuncAttributeMaxDynamicSharedMemorySize, k1_smem);
    const int k2_smem = SM_A0 + 8 * 2 * ASTB;   // 16384 + 69632 = 86016
    cudaFuncSetAttribute(k2_attn, cudaFuncAttributeMaxDynamicSharedMemorySize, k2_smem);

    k1_wh<<<NN / 64, 256, k1_smem>>>(h, W, a);
    k1bc<<<FRAG_BLOCKS + NN / 256, 256>>>();
    dnoop<<<1, 32>>>();                       // position k2 as 4th launch for ncu
    dim3 g2(KB, NN / MTILE);
    k2_attn<<<g2, 256, k2_smem>>>(A);
    k3_fin<<<(NN * OUT_DIM) / 1024, 256>>>(out);
}